// round 3
// baseline (speedup 1.0000x reference)
#include <cuda_runtime.h>
#include <math.h>

#define BATCH 8
#define LSEQ 1024
#define DIMC 256
#define NHEADS 8
#define DHEAD 32
#define ECH 64
#define PDIM 1024
#define NPATCH 8192   // BATCH*LSEQ
#define BHDIM 64      // BATCH*NHEADS

// ---------------- scratch (device globals; no allocations allowed) ----------
__device__ float g_conv[NPATCH * ECH * 64];   // [patch][ec][8*8]  128 MB
__device__ float g_stats[ECH * 2];            // mean, rstd per channel
__device__ float g_embin[NPATCH * PDIM];      // 32 MB
__device__ float g_x[NPATCH * DIMC];
__device__ float g_xn[NPATCH * DIMC];
__device__ float g_m[NPATCH * DIMC];          // m, later reused for mv
__device__ float g_q[BHDIM * LSEQ * DHEAD];
__device__ float g_k[BHDIM * LSEQ * DHEAD];
__device__ float g_v[NPATCH * DIMC];

__device__ __forceinline__ float gelu_f(float x) {
    return 0.5f * x * (1.0f + erff(x * 0.70710678118654752440f));
}

// ---------------- conv 3x3 stride2 pad1 on 16x16 patches --------------------
__global__ __launch_bounds__(256) void conv_kernel(
    const float* __restrict__ img, const float* __restrict__ w,
    const float* __restrict__ bias, float* __restrict__ out)
{
    int patch = blockIdx.x;            // b*1024 + gi*32 + gj
    int b  = patch >> 10;
    int gi = (patch >> 5) & 31;
    int gj = patch & 31;
    __shared__ float s_in[3][16][16];
    __shared__ float s_w[ECH * 27];
    int t = threadIdx.x;
    for (int i = t; i < 3 * 256; i += 256) {
        int c = i >> 8; int pi = (i >> 4) & 15; int pj = i & 15;
        s_in[c][pi][pj] = img[(((long)b * 3 + c) * 512 + gi * 16 + pi) * 512 + gj * 16 + pj];
    }
    for (int i = t; i < ECH * 27; i += 256) s_w[i] = w[i];
    __syncthreads();
#pragma unroll
    for (int j = 0; j < 16; j++) {
        int idx = t + 256 * j;         // 0..4095
        int oc = idx >> 6; int pos = idx & 63;
        int oy = pos >> 3, ox = pos & 7;
        float acc = bias[oc];
        const float* wp = &s_w[oc * 27];
        int iy0 = 2 * oy - 1, ix0 = 2 * ox - 1;
#pragma unroll
        for (int c = 0; c < 3; c++)
#pragma unroll
        for (int ky = 0; ky < 3; ky++) {
            int iy = iy0 + ky;
            if (iy < 0 || iy > 15) continue;
#pragma unroll
            for (int kx = 0; kx < 3; kx++) {
                int ix = ix0 + kx;
                if (ix < 0 || ix > 15) continue;
                acc += s_in[c][iy][ix] * wp[c * 9 + ky * 3 + kx];
            }
        }
        out[(long)patch * 4096 + idx] = acc;
    }
}

// ---------------- batchnorm statistics (per channel over 524288 elems) ------
__global__ __launch_bounds__(256) void bn_stats_kernel(
    const float* __restrict__ conv, float* __restrict__ stats)
{
    int c = blockIdx.x, t = threadIdx.x;
    double s = 0.0, ss = 0.0;
    for (int i = t; i < NPATCH * 64; i += 256) {
        int p = i >> 6, e = i & 63;
        float v = conv[(long)p * 4096 + c * 64 + e];
        s += v; ss += (double)v * v;
    }
    __shared__ double sh1[256], sh2[256];
    sh1[t] = s; sh2[t] = ss;
    __syncthreads();
    for (int o = 128; o > 0; o >>= 1) {
        if (t < o) { sh1[t] += sh1[t + o]; sh2[t] += sh2[t + o]; }
        __syncthreads();
    }
    if (t == 0) {
        double mean = sh1[0] / 524288.0;
        double var  = sh2[0] / 524288.0 - mean * mean;
        stats[2 * c]     = (float)mean;
        stats[2 * c + 1] = rsqrtf((float)var + 1e-5f);
    }
}

// ---------------- BN + exact GELU + maxpool 3x3/s2/p1 + flatten -------------
__global__ __launch_bounds__(256) void bn_gelu_pool_kernel(
    const float* __restrict__ conv, const float* __restrict__ stats,
    const float* __restrict__ bn_g, const float* __restrict__ bn_b,
    float* __restrict__ out)
{
    int patch = blockIdx.x;
    __shared__ float s[ECH * 64];      // 16 KB
    int t = threadIdx.x;
    for (int i = t; i < ECH * 64; i += 256) {
        int c = i >> 6;
        float mean = stats[2 * c], rstd = stats[2 * c + 1];
        float x = (conv[(long)patch * 4096 + i] - mean) * rstd * bn_g[c] + bn_b[c];
        s[i] = gelu_f(x);
    }
    __syncthreads();
    for (int i = t; i < ECH * 16; i += 256) {
        int c = i >> 4; int pos = i & 15;
        int oy = pos >> 2, ox = pos & 3;
        float m = -INFINITY;
        for (int wy = 2 * oy - 1; wy <= 2 * oy + 1; wy++) {
            if (wy < 0 || wy > 7) continue;
            for (int wx = 2 * ox - 1; wx <= 2 * ox + 1; wx++) {
                if (wx < 0 || wx > 7) continue;
                m = fmaxf(m, s[c * 64 + wy * 8 + wx]);
            }
        }
        out[(long)patch * PDIM + i] = m;   // PD index = c*16 + oy*4 + ox
    }
}

// ---------------- generic NN SGEMM: C = A@B (+bias) (+res), batched via z ---
__global__ __launch_bounds__(256) void sgemm_nn(
    const float* __restrict__ A, const float* __restrict__ Bm,
    const float* __restrict__ bias, const float* __restrict__ res,
    float* __restrict__ C, int K,
    long zA, long zB, long zRes, long zC,
    int lda, int ldb, int ldres, int ldc)
{
    long bz = blockIdx.z;
    A += zA * bz; Bm += zB * bz; C += zC * bz;
    if (res) res += zRes * bz;
    int m0 = blockIdx.y * 64, n0 = blockIdx.x * 64;
    __shared__ float As[16][68];
    __shared__ float Bs[16][68];
    int t = threadIdx.x;
    int tx = t & 15, ty = t >> 4;
    int la_m = t >> 2, la_k = (t & 3) << 2;
    int lb_k = t >> 4, lb_n = (t & 15) << 2;
    float acc[4][4] = {};
    for (int k0 = 0; k0 < K; k0 += 16) {
        float4 av = *(const float4*)(A + (long)(m0 + la_m) * lda + k0 + la_k);
        As[la_k + 0][la_m] = av.x;
        As[la_k + 1][la_m] = av.y;
        As[la_k + 2][la_m] = av.z;
        As[la_k + 3][la_m] = av.w;
        *(float4*)&Bs[lb_k][lb_n] = *(const float4*)(Bm + (long)(k0 + lb_k) * ldb + n0 + lb_n);
        __syncthreads();
#pragma unroll
        for (int kk = 0; kk < 16; kk++) {
            float4 a = *(const float4*)&As[kk][ty << 2];
            float4 b = *(const float4*)&Bs[kk][tx << 2];
            acc[0][0] += a.x * b.x; acc[0][1] += a.x * b.y; acc[0][2] += a.x * b.z; acc[0][3] += a.x * b.w;
            acc[1][0] += a.y * b.x; acc[1][1] += a.y * b.y; acc[1][2] += a.y * b.z; acc[1][3] += a.y * b.w;
            acc[2][0] += a.z * b.x; acc[2][1] += a.z * b.y; acc[2][2] += a.z * b.z; acc[2][3] += a.z * b.w;
            acc[3][0] += a.w * b.x; acc[3][1] += a.w * b.y; acc[3][2] += a.w * b.z; acc[3][3] += a.w * b.w;
        }
        __syncthreads();
    }
#pragma unroll
    for (int i = 0; i < 4; i++) {
        int m = m0 + (ty << 2) + i;
#pragma unroll
        for (int j = 0; j < 4; j++) {
            int n = n0 + (tx << 2) + j;
            float v = acc[i][j];
            if (bias) v += bias[n];
            if (res)  v += res[(long)m * ldres + n];
            C[(long)m * ldc + n] = v;
        }
    }
}

// ---------------- layernorm over 256 columns --------------------------------
__global__ __launch_bounds__(256) void ln_kernel(
    const float* __restrict__ x, const float* __restrict__ g,
    const float* __restrict__ bb, float* __restrict__ o)
{
    int row = blockIdx.x, t = threadIdx.x;
    float v = x[(long)row * DIMC + t];
    int lane = t & 31, warp = t >> 5;
    __shared__ float sh[8];
    float s = v;
#pragma unroll
    for (int k = 16; k; k >>= 1) s += __shfl_xor_sync(0xffffffffu, s, k);
    if (lane == 0) sh[warp] = s;
    __syncthreads();
    float mean = (sh[0] + sh[1] + sh[2] + sh[3] + sh[4] + sh[5] + sh[6] + sh[7]) * (1.0f / 256.0f);
    float d = v - mean;
    float q = d * d;
#pragma unroll
    for (int k = 16; k; k >>= 1) q += __shfl_xor_sync(0xffffffffu, q, k);
    __syncthreads();
    if (lane == 0) sh[warp] = q;
    __syncthreads();
    float var = (sh[0] + sh[1] + sh[2] + sh[3] + sh[4] + sh[5] + sh[6] + sh[7]) * (1.0f / 256.0f);
    float rstd = rsqrtf(var + 1e-5f);
    o[(long)row * DIMC + t] = d * rstd * g[t] + bb[t];
}

// ---------------- qk = relu(m_h @ W(32x64) + b); split q/k ------------------
__global__ __launch_bounds__(256) void qk_kernel(
    const float* __restrict__ m, const float* __restrict__ W,
    const float* __restrict__ bias, float* __restrict__ q, float* __restrict__ k)
{
    __shared__ float sm[16][DIMC];   // 16 KB
    __shared__ float sw[32 * 64];    // 8 KB
    __shared__ float sb[64];
    int t = threadIdx.x;
    int r0 = blockIdx.x * 16;
    for (int i = t; i < 16 * DIMC; i += 256)
        sm[i >> 8][i & 255] = m[(long)(r0 + (i >> 8)) * DIMC + (i & 255)];
    for (int i = t; i < 2048; i += 256) sw[i] = W[i];
    if (t < 64) sb[t] = bias[t];
    __syncthreads();
    for (int o = t; o < 8192; o += 256) {
        int r = o >> 9;
        int rem = o & 511;
        int h = rem >> 6;
        int e = rem & 63;
        float acc = sb[e];
#pragma unroll
        for (int c = 0; c < 32; c++) acc += sm[r][h * 32 + c] * sw[c * 64 + e];
        acc = fmaxf(acc, 0.0f);
        int row = r0 + r;
        int b = row >> 10, l = row & 1023;
        int bh = b * 8 + h;
        if (e < 32) q[((long)bh * LSEQ + l) * 32 + e] = acc;
        else        k[((long)bh * LSEQ + l) * 32 + (e - 32)] = acc;
    }
}

// ---------------- score = (Q @ K^T) / 32 per (b,h) --------------------------
__global__ __launch_bounds__(256) void score_kernel(
    const float* __restrict__ q, const float* __restrict__ kk_,
    float* __restrict__ out)
{
    long z = blockIdx.z;
    const float* Q = q   + z * LSEQ * DHEAD;
    const float* K = kk_ + z * LSEQ * DHEAD;
    float* C = out + z * (long)LSEQ * LSEQ;
    int m0 = blockIdx.y * 64, n0 = blockIdx.x * 64;
    __shared__ float Qs[32][68], Ks[32][68];
    int t = threadIdx.x;
    {
        int lane_k = t & 31, rbase = t >> 5;
#pragma unroll
        for (int l = 0; l < 8; l++) {
            int r = rbase + l * 8;
            Qs[lane_k][r] = Q[(long)(m0 + r) * 32 + lane_k];
            Ks[lane_k][r] = K[(long)(n0 + r) * 32 + lane_k];
        }
    }
    __syncthreads();
    int tx = t & 15, ty = t >> 4;
    float acc[4][4] = {};
#pragma unroll
    for (int kc = 0; kc < 32; kc++) {
        float4 a = *(const float4*)&Qs[kc][ty << 2];
        float4 b = *(const float4*)&Ks[kc][tx << 2];
        acc[0][0] += a.x * b.x; acc[0][1] += a.x * b.y; acc[0][2] += a.x * b.z; acc[0][3] += a.x * b.w;
        acc[1][0] += a.y * b.x; acc[1][1] += a.y * b.y; acc[1][2] += a.y * b.z; acc[1][3] += a.y * b.w;
        acc[2][0] += a.z * b.x; acc[2][1] += a.z * b.y; acc[2][2] += a.z * b.z; acc[2][3] += a.z * b.w;
        acc[3][0] += a.w * b.x; acc[3][1] += a.w * b.y; acc[3][2] += a.w * b.z; acc[3][3] += a.w * b.w;
    }
    const float alpha = 1.0f / 32.0f;   // DIM^-0.5 / 2
#pragma unroll
    for (int i = 0; i < 4; i++)
#pragma unroll
    for (int j = 0; j < 4; j++)
        C[(long)(m0 + (ty << 2) + i) * LSEQ + n0 + (tx << 2) + j] = acc[i][j] * alpha;
}

// ---------------- row softmax over 1024 cols, in place ----------------------
__global__ __launch_bounds__(256) void softmax_kernel(float* __restrict__ a)
{
    long row = blockIdx.x;
    float* p = a + row * 1024;
    int t = threadIdx.x, lane = t & 31, warp = t >> 5;
    __shared__ float sh[8];
    float4 v = *(float4*)&p[t * 4];
    float mx = fmaxf(fmaxf(v.x, v.y), fmaxf(v.z, v.w));
#pragma unroll
    for (int k = 16; k; k >>= 1) mx = fmaxf(mx, __shfl_xor_sync(0xffffffffu, mx, k));
    if (lane == 0) sh[warp] = mx;
    __syncthreads();
    mx = fmaxf(fmaxf(fmaxf(sh[0], sh[1]), fmaxf(sh[2], sh[3])),
               fmaxf(fmaxf(sh[4], sh[5]), fmaxf(sh[6], sh[7])));
    v.x = expf(v.x - mx); v.y = expf(v.y - mx);
    v.z = expf(v.z - mx); v.w = expf(v.w - mx);
    float s = v.x + v.y + v.z + v.w;
#pragma unroll
    for (int k = 16; k; k >>= 1) s += __shfl_xor_sync(0xffffffffu, s, k);
    __syncthreads();
    if (lane == 0) sh[warp] = s;
    __syncthreads();
    float tot = sh[0] + sh[1] + sh[2] + sh[3] + sh[4] + sh[5] + sh[6] + sh[7];
    float inv = 1.0f / tot;
    v.x *= inv; v.y *= inv; v.z *= inv; v.w *= inv;
    *(float4*)&p[t * 4] = v;
}

// ---------------- mv = attn @ xh + xh per (b,h): M=1024,N=32,K=1024 ---------
__global__ __launch_bounds__(256) void mv_kernel(
    const float* __restrict__ attn, const float* __restrict__ xn,
    float* __restrict__ out)
{
    int z = blockIdx.z;
    int b = z >> 3, h = z & 7;
    const float* A  = attn + (long)z * LSEQ * LSEQ;
    const float* Bm = xn + (long)b * LSEQ * DIMC + h * 32;
    float* C = out + (long)b * LSEQ * DIMC + h * 32;
    int m0 = blockIdx.x * 64;
    __shared__ float As[16][66];
    __shared__ float Bs[16][32];
    int t = threadIdx.x;
    int tx = t & 7, ty = t >> 3;     // tx: 4 cols each, ty: 2 rows each
    int la_m = t >> 2, la_k = (t & 3) << 2;
    float acc[2][4] = {};
    for (int k0 = 0; k0 < LSEQ; k0 += 16) {
        float4 av = *(const float4*)(A + (long)(m0 + la_m) * LSEQ + k0 + la_k);
        As[la_k + 0][la_m] = av.x;
        As[la_k + 1][la_m] = av.y;
        As[la_k + 2][la_m] = av.z;
        As[la_k + 3][la_m] = av.w;
        {
            int i = t;
            Bs[i >> 5][i & 31] = Bm[(long)(k0 + (i >> 5)) * DIMC + (i & 31)];
            i = t + 256;
            Bs[i >> 5][i & 31] = Bm[(long)(k0 + (i >> 5)) * DIMC + (i & 31)];
        }
        __syncthreads();
#pragma unroll
        for (int kc = 0; kc < 16; kc++) {
            float2 a = *(const float2*)&As[kc][ty << 1];
            float4 bv = *(const float4*)&Bs[kc][tx << 2];
            acc[0][0] += a.x * bv.x; acc[0][1] += a.x * bv.y; acc[0][2] += a.x * bv.z; acc[0][3] += a.x * bv.w;
            acc[1][0] += a.y * bv.x; acc[1][1] += a.y * bv.y; acc[1][2] += a.y * bv.z; acc[1][3] += a.y * bv.w;
        }
        __syncthreads();
    }
#pragma unroll
    for (int i = 0; i < 2; i++) {
        int m = m0 + (ty << 1) + i;
#pragma unroll
        for (int j = 0; j < 4; j++) {
            int n = (tx << 2) + j;
            C[(long)m * DIMC + n] = acc[i][j] + Bm[(long)m * DIMC + n];
        }
    }
}

// ---------------- v = gelu(relu(mv_h @ vW(32x32) + vb)) ---------------------
__global__ __launch_bounds__(256) void v_kernel(
    const float* __restrict__ mv, const float* __restrict__ W,
    const float* __restrict__ bias, float* __restrict__ out)
{
    __shared__ float sm[16][DIMC];
    __shared__ float sw[32 * 32];
    __shared__ float sb[32];
    int t = threadIdx.x;
    int r0 = blockIdx.x * 16;
    for (int i = t; i < 16 * DIMC; i += 256)
        sm[i >> 8][i & 255] = mv[(long)(r0 + (i >> 8)) * DIMC + (i & 255)];
    for (int i = t; i < 1024; i += 256) sw[i] = W[i];
    if (t < 32) sb[t] = bias[t];
    __syncthreads();
    for (int o = t; o < 4096; o += 256) {
        int r = o >> 8, col = o & 255;
        int h = col >> 5, d = col & 31;
        float acc = sb[d];
#pragma unroll
        for (int c = 0; c < 32; c++) acc += sm[r][h * 32 + c] * sw[c * 32 + d];
        acc = fmaxf(acc, 0.0f);
        out[(long)(r0 + r) * DIMC + col] = gelu_f(acc);
    }
}

// ---------------- host orchestration ----------------------------------------
extern "C" void kernel_launch(void* const* d_in, const int* in_sizes, int n_in,
                              void* d_out, int out_size)
{
    (void)in_sizes; (void)n_in; (void)out_size;
    const float* img    = (const float*)d_in[0];
    const float* adj    = (const float*)d_in[1];
    const float* conv_w = (const float*)d_in[3];
    const float* conv_b = (const float*)d_in[4];
    const float* bn_g   = (const float*)d_in[5];
    const float* bn_b   = (const float*)d_in[6];
    const float* emb_w  = (const float*)d_in[7];
    const float* emb_b  = (const float*)d_in[8];
    const float* ln_g   = (const float*)d_in[9];
    const float* ln_b   = (const float*)d_in[10];
    const float* qk_w   = (const float*)d_in[11];
    const float* qk_b   = (const float*)d_in[12];
    const float* v_w    = (const float*)d_in[13];
    const float* v_b    = (const float*)d_in[14];
    const float* proj_w = (const float*)d_in[15];
    float* out = (float*)d_out;

    float *p_conv, *p_stats, *p_embin, *p_x, *p_xn, *p_m, *p_q, *p_k, *p_v;
    cudaGetSymbolAddress((void**)&p_conv,  g_conv);
    cudaGetSymbolAddress((void**)&p_stats, g_stats);
    cudaGetSymbolAddress((void**)&p_embin, g_embin);
    cudaGetSymbolAddress((void**)&p_x,     g_x);
    cudaGetSymbolAddress((void**)&p_xn,    g_xn);
    cudaGetSymbolAddress((void**)&p_m,     g_m);
    cudaGetSymbolAddress((void**)&p_q,     g_q);
    cudaGetSymbolAddress((void**)&p_k,     g_k);
    cudaGetSymbolAddress((void**)&p_v,     g_v);

    conv_kernel<<<NPATCH, 256>>>(img, conv_w, conv_b, p_conv);
    bn_stats_kernel<<<ECH, 256>>>(p_conv, p_stats);
    bn_gelu_pool_kernel<<<NPATCH, 256>>>(p_conv, p_stats, bn_g, bn_b, p_embin);

    // embedding: (8192x1024) @ (1024x256) + bias
    sgemm_nn<<<dim3(DIMC / 64, NPATCH / 64, 1), 256>>>(
        p_embin, emb_w, emb_b, nullptr, p_x, PDIM,
        0, 0, 0, 0, PDIM, DIMC, 0, DIMC);

    const long LD = (long)LSEQ * DIMC;
    for (int i = 0; i < 4; i++) {
        ln_kernel<<<NPATCH, 256>>>(p_x, ln_g + i * DIMC, ln_b + i * DIMC, p_xn);
        // m = A @ xn + xn  per batch: M=1024, N=256, K=1024
        sgemm_nn<<<dim3(DIMC / 64, LSEQ / 64, BATCH), 256>>>(
            adj, p_xn, nullptr, p_xn, p_m, LSEQ,
            0, LD, LD, LD, LSEQ, DIMC, DIMC, DIMC);
        qk_kernel<<<NPATCH / 16, 256>>>(p_m, qk_w + i * DHEAD * 2 * DHEAD,
                                        qk_b + i * 2 * DHEAD, p_q, p_k);
        score_kernel<<<dim3(16, 16, BHDIM), 256>>>(p_q, p_k, out);
        softmax_kernel<<<BHDIM * LSEQ, 256>>>(out);
        if (i < 3) {
            mv_kernel<<<dim3(16, 1, BHDIM), 256>>>(out, p_xn, p_m);
            v_kernel<<<NPATCH / 16, 256>>>(p_m, v_w + i * DHEAD * DHEAD,
                                           v_b + i * DHEAD, p_v);
            // x = v @ proj_w + xn : M=8192, N=256, K=256
            sgemm_nn<<<dim3(DIMC / 64, NPATCH / 64, 1), 256>>>(
                p_v, proj_w + i * DIMC * DIMC, nullptr, p_xn, p_x, DIMC,
                0, 0, 0, 0, DIMC, DIMC, DIMC, DIMC);
        }
    }
}

// round 7
// speedup vs baseline: 1.6526x; 1.6526x over previous
#include <cuda_runtime.h>
#include <math.h>

#define BATCH 8
#define LSEQ 1024
#define DIMC 256
#define NHEADS 8
#define DHEAD 32
#define ECH 64
#define PDIM 1024
#define NPATCH 8192   // BATCH*LSEQ
#define BHDIM 64      // BATCH*NHEADS

// ---------------- scratch (device globals; no allocations allowed) ----------
__device__ float g_conv[NPATCH * ECH * 64];   // 128 MB
__device__ float g_stats[ECH * 2];
__device__ float g_embin[NPATCH * PDIM];
__device__ float g_x[NPATCH * DIMC];
__device__ float g_xn[NPATCH * DIMC];
__device__ float g_m[NPATCH * DIMC];
__device__ float g_q[BHDIM * LSEQ * DHEAD];
__device__ float g_kt[BHDIM * DHEAD * LSEQ];  // K transposed: [bh][d][l]
__device__ float g_v[NPATCH * DIMC];

__device__ __forceinline__ float gelu_f(float x) {
    return 0.5f * x * (1.0f + erff(x * 0.70710678118654752440f));
}

// ---------------- conv 3x3 stride2 pad1 on 16x16 patches --------------------
__global__ __launch_bounds__(256) void conv_kernel(
    const float* __restrict__ img, const float* __restrict__ w,
    const float* __restrict__ bias, float* __restrict__ out)
{
    int patch = blockIdx.x;
    int b  = patch >> 10;
    int gi = (patch >> 5) & 31;
    int gj = patch & 31;
    __shared__ float s_in[3][16][16];
    __shared__ float s_w[ECH * 27];
    int t = threadIdx.x;
    for (int i = t; i < 3 * 256; i += 256) {
        int c = i >> 8; int pi = (i >> 4) & 15; int pj = i & 15;
        s_in[c][pi][pj] = img[(((long)b * 3 + c) * 512 + gi * 16 + pi) * 512 + gj * 16 + pj];
    }
    for (int i = t; i < ECH * 27; i += 256) s_w[i] = w[i];
    __syncthreads();
#pragma unroll
    for (int j = 0; j < 16; j++) {
        int idx = t + 256 * j;
        int oc = idx >> 6; int pos = idx & 63;
        int oy = pos >> 3, ox = pos & 7;
        float acc = bias[oc];
        const float* wp = &s_w[oc * 27];
        int iy0 = 2 * oy - 1, ix0 = 2 * ox - 1;
#pragma unroll
        for (int c = 0; c < 3; c++)
#pragma unroll
        for (int ky = 0; ky < 3; ky++) {
            int iy = iy0 + ky;
            if (iy < 0 || iy > 15) continue;
#pragma unroll
            for (int kx = 0; kx < 3; kx++) {
                int ix = ix0 + kx;
                if (ix < 0 || ix > 15) continue;
                acc += s_in[c][iy][ix] * wp[c * 9 + ky * 3 + kx];
            }
        }
        out[(long)patch * 4096 + idx] = acc;
    }
}

// ---------------- batchnorm statistics --------------------------------------
__global__ __launch_bounds__(256) void bn_stats_kernel(
    const float* __restrict__ conv, float* __restrict__ stats)
{
    int c = blockIdx.x, t = threadIdx.x;
    double s = 0.0, ss = 0.0;
    for (int i = t; i < NPATCH * 64; i += 256) {
        int p = i >> 6, e = i & 63;
        float v = conv[(long)p * 4096 + c * 64 + e];
        s += v; ss += (double)v * v;
    }
    __shared__ double sh1[256], sh2[256];
    sh1[t] = s; sh2[t] = ss;
    __syncthreads();
    for (int o = 128; o > 0; o >>= 1) {
        if (t < o) { sh1[t] += sh1[t + o]; sh2[t] += sh2[t + o]; }
        __syncthreads();
    }
    if (t == 0) {
        double mean = sh1[0] / 524288.0;
        double var  = sh2[0] / 524288.0 - mean * mean;
        stats[2 * c]     = (float)mean;
        stats[2 * c + 1] = rsqrtf((float)var + 1e-5f);
    }
}

// ---------------- BN + GELU + maxpool + flatten -----------------------------
__global__ __launch_bounds__(256) void bn_gelu_pool_kernel(
    const float* __restrict__ conv, const float* __restrict__ stats,
    const float* __restrict__ bn_g, const float* __restrict__ bn_b,
    float* __restrict__ out)
{
    int patch = blockIdx.x;
    __shared__ float s[ECH * 64];
    int t = threadIdx.x;
    for (int i = t; i < ECH * 64; i += 256) {
        int c = i >> 6;
        float mean = stats[2 * c], rstd = stats[2 * c + 1];
        float x = (conv[(long)patch * 4096 + i] - mean) * rstd * bn_g[c] + bn_b[c];
        s[i] = gelu_f(x);
    }
    __syncthreads();
    for (int i = t; i < ECH * 16; i += 256) {
        int c = i >> 4; int pos = i & 15;
        int oy = pos >> 2, ox = pos & 3;
        float m = -INFINITY;
        for (int wy = 2 * oy - 1; wy <= 2 * oy + 1; wy++) {
            if (wy < 0 || wy > 7) continue;
            for (int wx = 2 * ox - 1; wx <= 2 * ox + 1; wx++) {
                if (wx < 0 || wx > 7) continue;
                m = fmaxf(m, s[c * 64 + wy * 8 + wx]);
            }
        }
        out[(long)patch * PDIM + i] = m;
    }
}

// ---------------- 128x128 SGEMM, 8x8 microtile: C = A@B (+bias)(+res) -------
__global__ __launch_bounds__(256, 2) void sgemm128(
    const float* __restrict__ A, const float* __restrict__ Bm,
    const float* __restrict__ bias, const float* __restrict__ res,
    float* __restrict__ C, int K,
    long zA, long zB, long zRes, long zC,
    int lda, int ldb, int ldres, int ldc)
{
    long bz = blockIdx.z;
    A += zA * bz; Bm += zB * bz; C += zC * bz;
    if (res) res += zRes * bz;
    int m0 = blockIdx.y * 128, n0 = blockIdx.x * 128;
    __shared__ float As[8][132];   // transposed A tile
    __shared__ float Bs[8][128];
    int t = threadIdx.x;
    int tx = t & 15, ty = t >> 4;
    int la_m = t >> 1, la_k = (t & 1) * 4;
    int lb_k = t >> 5, lb_n = (t & 31) * 4;
    float acc[8][8] = {};
    const float* Aptr = A + (long)(m0 + la_m) * lda + la_k;
    const float* Bptr = Bm + (long)lb_k * ldb + n0 + lb_n;
    for (int k0 = 0; k0 < K; k0 += 8) {
        float4 av = *(const float4*)(Aptr + k0);
        As[la_k + 0][la_m] = av.x;
        As[la_k + 1][la_m] = av.y;
        As[la_k + 2][la_m] = av.z;
        As[la_k + 3][la_m] = av.w;
        *(float4*)&Bs[lb_k][lb_n] = *(const float4*)(Bptr + (long)k0 * ldb);
        __syncthreads();
#pragma unroll
        for (int kk = 0; kk < 8; kk++) {
            float4 a0 = *(const float4*)&As[kk][ty << 2];
            float4 a1 = *(const float4*)&As[kk][64 + (ty << 2)];
            float4 b0 = *(const float4*)&Bs[kk][tx << 2];
            float4 b1 = *(const float4*)&Bs[kk][64 + (tx << 2)];
            float a[8] = {a0.x, a0.y, a0.z, a0.w, a1.x, a1.y, a1.z, a1.w};
            float b[8] = {b0.x, b0.y, b0.z, b0.w, b1.x, b1.y, b1.z, b1.w};
#pragma unroll
            for (int i = 0; i < 8; i++)
#pragma unroll
            for (int j = 0; j < 8; j++)
                acc[i][j] += a[i] * b[j];
        }
        __syncthreads();
    }
#pragma unroll
    for (int i = 0; i < 8; i++) {
        int m = m0 + ((i & 4) << 4) + (ty << 2) + (i & 3);
#pragma unroll
        for (int jh = 0; jh < 2; jh++) {
            int n = n0 + jh * 64 + (tx << 2);
            float4 v;
            v.x = acc[i][jh * 4 + 0]; v.y = acc[i][jh * 4 + 1];
            v.z = acc[i][jh * 4 + 2]; v.w = acc[i][jh * 4 + 3];
            if (bias) {
                v.x += bias[n]; v.y += bias[n + 1]; v.z += bias[n + 2]; v.w += bias[n + 3];
            }
            if (res) {
                float4 r = *(const float4*)(res + (long)m * ldres + n);
                v.x += r.x; v.y += r.y; v.z += r.z; v.w += r.w;
            }
            *(float4*)(C + (long)m * ldc + n) = v;
        }
    }
}

// ---------------- layernorm over 256 columns --------------------------------
__global__ __launch_bounds__(256) void ln_kernel(
    const float* __restrict__ x, const float* __restrict__ g,
    const float* __restrict__ bb, float* __restrict__ o)
{
    int row = blockIdx.x, t = threadIdx.x;
    float v = x[(long)row * DIMC + t];
    int lane = t & 31, warp = t >> 5;
    __shared__ float sh[8];
    float s = v;
#pragma unroll
    for (int k = 16; k; k >>= 1) s += __shfl_xor_sync(0xffffffffu, s, k);
    if (lane == 0) sh[warp] = s;
    __syncthreads();
    float mean = (sh[0] + sh[1] + sh[2] + sh[3] + sh[4] + sh[5] + sh[6] + sh[7]) * (1.0f / 256.0f);
    float d = v - mean;
    float q = d * d;
#pragma unroll
    for (int k = 16; k; k >>= 1) q += __shfl_xor_sync(0xffffffffu, q, k);
    __syncthreads();
    if (lane == 0) sh[warp] = q;
    __syncthreads();
    float var = (sh[0] + sh[1] + sh[2] + sh[3] + sh[4] + sh[5] + sh[6] + sh[7]) * (1.0f / 256.0f);
    float rstd = rsqrtf(var + 1e-5f);
    o[(long)row * DIMC + t] = d * rstd * g[t] + bb[t];
}

// ---------------- qk = relu(m_h @ W(32x64) + b); q row-major, k transposed --
__global__ __launch_bounds__(256) void qk_kernel(
    const float* __restrict__ m, const float* __restrict__ W,
    const float* __restrict__ bias, float* __restrict__ q, float* __restrict__ kt)
{
    __shared__ float sm[16][DIMC];
    __shared__ float sw[32 * 64];
    __shared__ float sb[64];
    int t = threadIdx.x;
    int r0 = blockIdx.x * 16;
    for (int i = t; i < 16 * DIMC; i += 256)
        sm[i >> 8][i & 255] = m[(long)(r0 + (i >> 8)) * DIMC + (i & 255)];
    for (int i = t; i < 2048; i += 256) sw[i] = W[i];
    if (t < 64) sb[t] = bias[t];
    __syncthreads();
    for (int o = t; o < 8192; o += 256) {
        int r = o >> 9;
        int rem = o & 511;
        int h = rem >> 6;
        int e = rem & 63;
        float acc = sb[e];
#pragma unroll
        for (int c = 0; c < 32; c++) acc += sm[r][h * 32 + c] * sw[c * 64 + e];
        acc = fmaxf(acc, 0.0f);
        int row = r0 + r;
        int b = row >> 10, l = row & 1023;
        int bh = b * 8 + h;
        if (e < 32) q[((long)bh * LSEQ + l) * 32 + e] = acc;
        else        kt[((long)bh * 32 + (e - 32)) * LSEQ + l] = acc;
    }
}

// ---------------- fused score+softmax: P = softmax(QK^T/32) -> out ----------
// 16 query rows per block, full 1024-key row resident in smem.
__global__ __launch_bounds__(256, 2) void attn_kernel(
    const float* __restrict__ q, const float* __restrict__ kt,
    float* __restrict__ out)
{
    extern __shared__ float smem[];
    float* Qs = smem;                    // [32][16] k-major
    float* Kg = smem + 512;              // [32][260] key slice (k-major)
    float* S  = smem + 512 + 32 * 260;   // [16][1028]
    int t = threadIdx.x;
    int bh = blockIdx.y;
    int r0 = blockIdx.x * 16;

    if (t < 128) {
        int r = t >> 3, k4 = (t & 7) * 4;
        float4 v = *(const float4*)(q + ((long)bh * LSEQ + r0 + r) * 32 + k4);
        Qs[(k4 + 0) * 16 + r] = v.x;
        Qs[(k4 + 1) * 16 + r] = v.y;
        Qs[(k4 + 2) * 16 + r] = v.z;
        Qs[(k4 + 3) * 16 + r] = v.w;
    }
    int tx = t & 63, ty = t >> 6;
    const float alpha = 1.0f / 32.0f;    // DIM^-0.5 / 2
    for (int g = 0; g < 4; g++) {
        __syncthreads();
        {
            int k = t >> 3;
            const float* src = kt + ((long)bh * 32 + k) * LSEQ + g * 256;
            float* dst = Kg + k * 260;
#pragma unroll
            for (int j = 0; j < 8; j++) {
                int c = ((t & 7) + 8 * j) * 4;
                *(float4*)(dst + c) = *(const float4*)(src + c);
            }
        }
        __syncthreads();
        float acc[4][4] = {};
#pragma unroll
        for (int k = 0; k < 32; k++) {
            float4 a = *(const float4*)&Qs[k * 16 + (ty << 2)];
            float4 b = *(const float4*)&Kg[k * 260 + (tx << 2)];
            acc[0][0] += a.x * b.x; acc[0][1] += a.x * b.y; acc[0][2] += a.x * b.z; acc[0][3] += a.x * b.w;
            acc[1][0] += a.y * b.x; acc[1][1] += a.y * b.y; acc[1][2] += a.y * b.z; acc[1][3] += a.y * b.w;
            acc[2][0] += a.z * b.x; acc[2][1] += a.z * b.y; acc[2][2] += a.z * b.z; acc[2][3] += a.z * b.w;
            acc[3][0] += a.w * b.x; acc[3][1] += a.w * b.y; acc[3][2] += a.w * b.z; acc[3][3] += a.w * b.w;
        }
#pragma unroll
        for (int i = 0; i < 4; i++) {
            float4 v;
            v.x = acc[i][0] * alpha; v.y = acc[i][1] * alpha;
            v.z = acc[i][2] * alpha; v.w = acc[i][3] * alpha;
            *(float4*)&S[((ty << 2) + i) * 1028 + g * 256 + (tx << 2)] = v;
        }
    }
    __syncthreads();
    // softmax: each warp handles 2 rows, row fully within warp
    int warp = t >> 5, lane = t & 31;
    for (int rr = 0; rr < 2; rr++) {
        int row = warp * 2 + rr;
        float* sp = S + row * 1028;
        float v[32];
        float mx = -INFINITY;
#pragma unroll
        for (int j = 0; j < 32; j++) { v[j] = sp[lane + 32 * j]; mx = fmaxf(mx, v[j]); }
#pragma unroll
        for (int o = 16; o; o >>= 1) mx = fmaxf(mx, __shfl_xor_sync(0xffffffffu, mx, o));
        float s = 0.0f;
#pragma unroll
        for (int j = 0; j < 32; j++) { v[j] = expf(v[j] - mx); s += v[j]; }
#pragma unroll
        for (int o = 16; o; o >>= 1) s += __shfl_xor_sync(0xffffffffu, s, o);
        float inv = 1.0f / s;
#pragma unroll
        for (int j = 0; j < 32; j++) sp[lane + 32 * j] = v[j] * inv;
    }
    __syncthreads();
    // coalesced write of normalized P
    float* op = out + ((long)bh * LSEQ + r0) * LSEQ;
#pragma unroll
    for (int j = 0; j < 16; j++) {
        int f = j * 256 + t;              // float4 index over 16x1024
        int row = f >> 8;
        int col = (f & 255) * 4;
        float4 v = *(const float4*)&S[row * 1028 + col];
        *(float4*)(op + (long)row * LSEQ + col) = v;
    }
}

// ---------------- mv = P @ xh + xh per (b,h): 128-row tiles -----------------
__global__ __launch_bounds__(256, 2) void mv128(
    const float* __restrict__ P, const float* __restrict__ xn,
    float* __restrict__ out)
{
    int z = blockIdx.y;
    int b = z >> 3, h = z & 7;
    const float* A  = P + (long)z * LSEQ * LSEQ;
    const float* Bm = xn + (long)b * LSEQ * DIMC + h * 32;
    float* C = out + (long)b * LSEQ * DIMC + h * 32;
    int m0 = blockIdx.x * 128;
    __shared__ float AsT[16][132];
    __shared__ float Bs[16][36];
    int t = threadIdx.x;
    int tx = t & 7, ty = t >> 3;
    int la_m = t >> 1, la_k = (t & 1) * 4;
    float acc[4][4] = {};
    const float* Aptr = A + (long)(m0 + la_m) * LSEQ + la_k;
    for (int k0 = 0; k0 < LSEQ; k0 += 16) {
        float4 a0 = *(const float4*)(Aptr + k0);
        float4 a1 = *(const float4*)(Aptr + k0 + 8);
        AsT[la_k + 0][la_m] = a0.x;
        AsT[la_k + 1][la_m] = a0.y;
        AsT[la_k + 2][la_m] = a0.z;
        AsT[la_k + 3][la_m] = a0.w;
        AsT[la_k + 8][la_m] = a1.x;
        AsT[la_k + 9][la_m] = a1.y;
        AsT[la_k + 10][la_m] = a1.z;
        AsT[la_k + 11][la_m] = a1.w;
        if (t < 128) {
            int row = t >> 3, c4 = (t & 7) * 4;
            *(float4*)&Bs[row][c4] = *(const float4*)(Bm + (long)(k0 + row) * DIMC + c4);
        }
        __syncthreads();
#pragma unroll
        for (int kk = 0; kk < 16; kk++) {
            float4 a = *(const float4*)&AsT[kk][ty << 2];
            float4 bv = *(const float4*)&Bs[kk][tx << 2];
            acc[0][0] += a.x * bv.x; acc[0][1] += a.x * bv.y; acc[0][2] += a.x * bv.z; acc[0][3] += a.x * bv.w;
            acc[1][0] += a.y * bv.x; acc[1][1] += a.y * bv.y; acc[1][2] += a.y * bv.z; acc[1][3] += a.y * bv.w;
            acc[2][0] += a.z * bv.x; acc[2][1] += a.z * bv.y; acc[2][2] += a.z * bv.z; acc[2][3] += a.z * bv.w;
            acc[3][0] += a.w * bv.x; acc[3][1] += a.w * bv.y; acc[3][2] += a.w * bv.z; acc[3][3] += a.w * bv.w;
        }
        __syncthreads();
    }
#pragma unroll
    for (int i = 0; i < 4; i++) {
        int m = m0 + (ty << 2) + i;
        float4 r = *(const float4*)(Bm + (long)m * DIMC + (tx << 2));
        float4 v;
        v.x = acc[i][0] + r.x; v.y = acc[i][1] + r.y;
        v.z = acc[i][2] + r.z; v.w = acc[i][3] + r.w;
        *(float4*)(C + (long)m * DIMC + (tx << 2)) = v;
    }
}

// ---------------- v = gelu(relu(mv_h @ vW(32x32) + vb)) ---------------------
__global__ __launch_bounds__(256) void v_kernel(
    const float* __restrict__ mv, const float* __restrict__ W,
    const float* __restrict__ bias, float* __restrict__ out)
{
    __shared__ float sm[16][DIMC];
    __shared__ float sw[32 * 32];
    __shared__ float sb[32];
    int t = threadIdx.x;
    int r0 = blockIdx.x * 16;
    for (int i = t; i < 16 * DIMC; i += 256)
        sm[i >> 8][i & 255] = mv[(long)(r0 + (i >> 8)) * DIMC + (i & 255)];
    for (int i = t; i < 1024; i += 256) sw[i] = W[i];
    if (t < 32) sb[t] = bias[t];
    __syncthreads();
    for (int o = t; o < 4096; o += 256) {
        int r = o >> 8, col = o & 255;
        int h = col >> 5, d = col & 31;
        float acc = sb[d];
#pragma unroll
        for (int c = 0; c < 32; c++) acc += sm[r][h * 32 + c] * sw[c * 32 + d];
        acc = fmaxf(acc, 0.0f);
        out[(long)(r0 + r) * DIMC + col] = gelu_f(acc);
    }
}

// ---------------- host orchestration ----------------------------------------
extern "C" void kernel_launch(void* const* d_in, const int* in_sizes, int n_in,
                              void* d_out, int out_size)
{
    (void)in_sizes; (void)n_in; (void)out_size;
    const float* img    = (const float*)d_in[0];
    const float* adj    = (const float*)d_in[1];
    const float* conv_w = (const float*)d_in[3];
    const float* conv_b = (const float*)d_in[4];
    const float* bn_g   = (const float*)d_in[5];
    const float* bn_b   = (const float*)d_in[6];
    const float* emb_w  = (const float*)d_in[7];
    const float* emb_b  = (const float*)d_in[8];
    const float* ln_g   = (const float*)d_in[9];
    const float* ln_b   = (const float*)d_in[10];
    const float* qk_w   = (const float*)d_in[11];
    const float* qk_b   = (const float*)d_in[12];
    const float* v_w    = (const float*)d_in[13];
    const float* v_b    = (const float*)d_in[14];
    const float* proj_w = (const float*)d_in[15];
    float* out = (float*)d_out;

    float *p_conv, *p_stats, *p_embin, *p_x, *p_xn, *p_m, *p_q, *p_kt, *p_v;
    cudaGetSymbolAddress((void**)&p_conv,  g_conv);
    cudaGetSymbolAddress((void**)&p_stats, g_stats);
    cudaGetSymbolAddress((void**)&p_embin, g_embin);
    cudaGetSymbolAddress((void**)&p_x,     g_x);
    cudaGetSymbolAddress((void**)&p_xn,    g_xn);
    cudaGetSymbolAddress((void**)&p_m,     g_m);
    cudaGetSymbolAddress((void**)&p_q,     g_q);
    cudaGetSymbolAddress((void**)&p_kt,    g_kt);
    cudaGetSymbolAddress((void**)&p_v,     g_v);

    static int attn_smem_set = 0;
    const int ATTN_SMEM = (512 + 32 * 260 + 16 * 1028) * 4;   // 101120 B
    if (!attn_smem_set) {
        cudaFuncSetAttribute(attn_kernel,
                             cudaFuncAttributeMaxDynamicSharedMemorySize, ATTN_SMEM);
        attn_smem_set = 1;
    }

    conv_kernel<<<NPATCH, 256>>>(img, conv_w, conv_b, p_conv);
    bn_stats_kernel<<<ECH, 256>>>(p_conv, p_stats);
    bn_gelu_pool_kernel<<<NPATCH, 256>>>(p_conv, p_stats, bn_g, bn_b, p_embin);

    // embedding: (8192x1024) @ (1024x256) + bias
    sgemm128<<<dim3(DIMC / 128, NPATCH / 128, 1), 256>>>(
        p_embin, emb_w, emb_b, nullptr, p_x, PDIM,
        0, 0, 0, 0, PDIM, DIMC, 0, DIMC);

    const long LD = (long)LSEQ * DIMC;
    for (int i = 0; i < 4; i++) {
        ln_kernel<<<NPATCH, 256>>>(p_x, ln_g + i * DIMC, ln_b + i * DIMC, p_xn);
        // m = A @ xn + xn  per batch: M=1024, N=256, K=1024
        sgemm128<<<dim3(DIMC / 128, LSEQ / 128, BATCH), 256>>>(
            adj, p_xn, nullptr, p_xn, p_m, LSEQ,
            0, LD, LD, LD, LSEQ, DIMC, DIMC, DIMC);
        qk_kernel<<<NPATCH / 16, 256>>>(p_m, qk_w + i * DHEAD * 2 * DHEAD,
                                        qk_b + i * 2 * DHEAD, p_q, p_kt);
        attn_kernel<<<dim3(LSEQ / 16, BHDIM), 256, ATTN_SMEM>>>(p_q, p_kt, out);
        if (i < 3) {
            mv128<<<dim3(LSEQ / 128, BHDIM), 256>>>(out, p_xn, p_m);
            v_kernel<<<NPATCH / 16, 256>>>(p_m, v_w + i * DHEAD * DHEAD,
                                           v_b + i * DHEAD, p_v);
            // x = v @ proj_w + xn : M=8192, N=256, K=256
            sgemm128<<<dim3(DIMC / 128, NPATCH / 128, 1), 256>>>(
                p_v, proj_w + i * DIMC * DIMC, nullptr, p_xn, p_x, DIMC,
                0, 0, 0, 0, DIMC, DIMC, DIMC, DIMC);
        }
    }
}

// round 8
// speedup vs baseline: 2.0665x; 1.2505x over previous
#include <cuda_runtime.h>
#include <math.h>

#define BATCH 8
#define LSEQ 1024
#define DIMC 256
#define NHEADS 8
#define DHEAD 32
#define ECH 64
#define PDIM 1024
#define NPATCH 8192   // BATCH*LSEQ
#define BHDIM 64      // BATCH*NHEADS

// ---------------- scratch (device globals; no allocations allowed) ----------
__device__ float g_conv[NPATCH * ECH * 64];   // 128 MB
__device__ float g_part[NPATCH * 128];        // per-patch per-channel {sum,ss}
__device__ float g_stats[ECH * 2];
__device__ float g_embin[NPATCH * PDIM];
__device__ float g_x[NPATCH * DIMC];
__device__ float g_xn[NPATCH * DIMC];
__device__ float g_m[NPATCH * DIMC];
__device__ float g_q[BHDIM * LSEQ * DHEAD];
__device__ float g_kt[BHDIM * DHEAD * LSEQ];  // K transposed: [bh][d][l]
__device__ float g_v[NPATCH * DIMC];

__device__ __forceinline__ float gelu_f(float x) {
    return 0.5f * x * (1.0f + erff(x * 0.70710678118654752440f));
}

// ---------------- conv 3x3 stride2 pad1 + per-patch BN partial sums ---------
__global__ __launch_bounds__(256) void conv_kernel(
    const float* __restrict__ img, const float* __restrict__ w,
    const float* __restrict__ bias, float* __restrict__ out,
    float* __restrict__ part)
{
    int patch = blockIdx.x;
    int b  = patch >> 10;
    int gi = (patch >> 5) & 31;
    int gj = patch & 31;
    __shared__ float s_in[3][16][16];
    __shared__ float s_w[ECH * 27];
    __shared__ float s_vals[ECH * 64];   // 16 KB
    int t = threadIdx.x;
    for (int i = t; i < 3 * 256; i += 256) {
        int c = i >> 8; int pi = (i >> 4) & 15; int pj = i & 15;
        s_in[c][pi][pj] = img[(((long)b * 3 + c) * 512 + gi * 16 + pi) * 512 + gj * 16 + pj];
    }
    for (int i = t; i < ECH * 27; i += 256) s_w[i] = w[i];
    __syncthreads();
#pragma unroll
    for (int j = 0; j < 16; j++) {
        int idx = t + 256 * j;
        int oc = idx >> 6; int pos = idx & 63;
        int oy = pos >> 3, ox = pos & 7;
        float acc = bias[oc];
        const float* wp = &s_w[oc * 27];
        int iy0 = 2 * oy - 1, ix0 = 2 * ox - 1;
#pragma unroll
        for (int c = 0; c < 3; c++)
#pragma unroll
        for (int ky = 0; ky < 3; ky++) {
            int iy = iy0 + ky;
            if (iy < 0 || iy > 15) continue;
#pragma unroll
            for (int kx = 0; kx < 3; kx++) {
                int ix = ix0 + kx;
                if (ix < 0 || ix > 15) continue;
                acc += s_in[c][iy][ix] * wp[c * 9 + ky * 3 + kx];
            }
        }
        out[(long)patch * 4096 + idx] = acc;
        s_vals[idx] = acc;
    }
    __syncthreads();
    if (t < ECH) {                        // deterministic per-channel reduce
        float s = 0.0f, ss = 0.0f;
        const float* vp = &s_vals[t * 64];
#pragma unroll
        for (int i = 0; i < 64; i++) { float v = vp[i]; s += v; ss += v * v; }
        part[(long)patch * 128 + t]      = s;
        part[(long)patch * 128 + 64 + t] = ss;
    }
}

// ---------------- BN statistics from per-patch partials (4 MB) --------------
__global__ __launch_bounds__(256) void bn_stats_kernel(
    const float* __restrict__ part, float* __restrict__ stats)
{
    int c = blockIdx.x, t = threadIdx.x;
    double s = 0.0, ss = 0.0;
    for (int p = t; p < NPATCH; p += 256) {
        s  += (double)part[(long)p * 128 + c];
        ss += (double)part[(long)p * 128 + 64 + c];
    }
    __shared__ double sh1[256], sh2[256];
    sh1[t] = s; sh2[t] = ss;
    __syncthreads();
    for (int o = 128; o > 0; o >>= 1) {
        if (t < o) { sh1[t] += sh1[t + o]; sh2[t] += sh2[t + o]; }
        __syncthreads();
    }
    if (t == 0) {
        double mean = sh1[0] / 524288.0;
        double var  = sh2[0] / 524288.0 - mean * mean;
        stats[2 * c]     = (float)mean;
        stats[2 * c + 1] = rsqrtf((float)var + 1e-5f);
    }
}

// ---------------- BN + GELU + maxpool + flatten -----------------------------
__global__ __launch_bounds__(256) void bn_gelu_pool_kernel(
    const float* __restrict__ conv, const float* __restrict__ stats,
    const float* __restrict__ bn_g, const float* __restrict__ bn_b,
    float* __restrict__ out)
{
    int patch = blockIdx.x;
    __shared__ float s[ECH * 64];
    int t = threadIdx.x;
    for (int i = t; i < ECH * 64; i += 256) {
        int c = i >> 6;
        float mean = stats[2 * c], rstd = stats[2 * c + 1];
        float x = (conv[(long)patch * 4096 + i] - mean) * rstd * bn_g[c] + bn_b[c];
        s[i] = gelu_f(x);
    }
    __syncthreads();
    for (int i = t; i < ECH * 16; i += 256) {
        int c = i >> 4; int pos = i & 15;
        int oy = pos >> 2, ox = pos & 3;
        float m = -INFINITY;
        for (int wy = 2 * oy - 1; wy <= 2 * oy + 1; wy++) {
            if (wy < 0 || wy > 7) continue;
            for (int wx = 2 * ox - 1; wx <= 2 * ox + 1; wx++) {
                if (wx < 0 || wx > 7) continue;
                m = fmaxf(m, s[c * 64 + wy * 8 + wx]);
            }
        }
        out[(long)patch * PDIM + i] = m;
    }
}

// ---------------- 128x64 double-buffered SGEMM, 8x4 microtile ---------------
__global__ __launch_bounds__(256, 3) void sgemm_db(
    const float* __restrict__ A, const float* __restrict__ Bm,
    const float* __restrict__ bias, const float* __restrict__ res,
    float* __restrict__ C, int K,
    long zA, long zB, long zRes, long zC,
    int lda, int ldb, int ldres, int ldc)
{
    long bz = blockIdx.z;
    A += zA * bz; Bm += zB * bz; C += zC * bz;
    if (res) res += zRes * bz;
    int m0 = blockIdx.y * 128, n0 = blockIdx.x * 64;
    __shared__ float As[2][8][132];
    __shared__ float Bs[2][8][68];
    int t = threadIdx.x;
    int tx = t & 15, ty = t >> 4;
    int la_m = t >> 1, la_k = (t & 1) * 4;
    int lb_k = t >> 5, lb_n = (t & 31) * 2;
    const float* Aptr = A + (long)(m0 + la_m) * lda + la_k;
    const float* Bptr = Bm + (long)lb_k * ldb + n0 + lb_n;
    float4 ar = *(const float4*)Aptr;
    float2 br = *(const float2*)Bptr;
    float acc[8][4] = {};
    int buf = 0;
    for (int k0 = 0; k0 < K; k0 += 8) {
        As[buf][la_k + 0][la_m] = ar.x;
        As[buf][la_k + 1][la_m] = ar.y;
        As[buf][la_k + 2][la_m] = ar.z;
        As[buf][la_k + 3][la_m] = ar.w;
        *(float2*)&Bs[buf][lb_k][lb_n] = br;
        __syncthreads();
        if (k0 + 8 < K) {
            ar = *(const float4*)(Aptr + k0 + 8);
            br = *(const float2*)(Bptr + (long)(k0 + 8) * ldb);
        }
#pragma unroll
        for (int kk = 0; kk < 8; kk++) {
            float4 a0 = *(const float4*)&As[buf][kk][ty << 2];
            float4 a1 = *(const float4*)&As[buf][kk][64 + (ty << 2)];
            float4 b  = *(const float4*)&Bs[buf][kk][tx << 2];
            float a[8] = {a0.x, a0.y, a0.z, a0.w, a1.x, a1.y, a1.z, a1.w};
#pragma unroll
            for (int i = 0; i < 8; i++) {
                acc[i][0] += a[i] * b.x;
                acc[i][1] += a[i] * b.y;
                acc[i][2] += a[i] * b.z;
                acc[i][3] += a[i] * b.w;
            }
        }
        buf ^= 1;
    }
    int n = n0 + (tx << 2);
    float4 bv = make_float4(0.f, 0.f, 0.f, 0.f);
    if (bias) bv = *(const float4*)(bias + n);
#pragma unroll
    for (int i = 0; i < 8; i++) {
        int m = m0 + ((i & 4) << 4) + (ty << 2) + (i & 3);
        float4 v;
        v.x = acc[i][0] + bv.x; v.y = acc[i][1] + bv.y;
        v.z = acc[i][2] + bv.z; v.w = acc[i][3] + bv.w;
        if (res) {
            float4 r = *(const float4*)(res + (long)m * ldres + n);
            v.x += r.x; v.y += r.y; v.z += r.z; v.w += r.w;
        }
        *(float4*)(C + (long)m * ldc + n) = v;
    }
}

// ---------------- layernorm over 256 columns --------------------------------
__global__ __launch_bounds__(256) void ln_kernel(
    const float* __restrict__ x, const float* __restrict__ g,
    const float* __restrict__ bb, float* __restrict__ o)
{
    int row = blockIdx.x, t = threadIdx.x;
    float v = x[(long)row * DIMC + t];
    int lane = t & 31, warp = t >> 5;
    __shared__ float sh[8];
    float s = v;
#pragma unroll
    for (int k = 16; k; k >>= 1) s += __shfl_xor_sync(0xffffffffu, s, k);
    if (lane == 0) sh[warp] = s;
    __syncthreads();
    float mean = (sh[0] + sh[1] + sh[2] + sh[3] + sh[4] + sh[5] + sh[6] + sh[7]) * (1.0f / 256.0f);
    float d = v - mean;
    float q = d * d;
#pragma unroll
    for (int k = 16; k; k >>= 1) q += __shfl_xor_sync(0xffffffffu, q, k);
    __syncthreads();
    if (lane == 0) sh[warp] = q;
    __syncthreads();
    float var = (sh[0] + sh[1] + sh[2] + sh[3] + sh[4] + sh[5] + sh[6] + sh[7]) * (1.0f / 256.0f);
    float rstd = rsqrtf(var + 1e-5f);
    o[(long)row * DIMC + t] = d * rstd * g[t] + bb[t];
}

// ---------------- qk = relu(m_h @ W(32x64) + b); q row-major, k transposed --
__global__ __launch_bounds__(256) void qk_kernel(
    const float* __restrict__ m, const float* __restrict__ W,
    const float* __restrict__ bias, float* __restrict__ q, float* __restrict__ kt)
{
    __shared__ float sm[16][DIMC];
    __shared__ float sw[32 * 64];
    __shared__ float sb[64];
    int t = threadIdx.x;
    int r0 = blockIdx.x * 16;
    for (int i = t; i < 16 * DIMC; i += 256)
        sm[i >> 8][i & 255] = m[(long)(r0 + (i >> 8)) * DIMC + (i & 255)];
    for (int i = t; i < 2048; i += 256) sw[i] = W[i];
    if (t < 64) sb[t] = bias[t];
    __syncthreads();
    for (int o = t; o < 8192; o += 256) {
        int r = o >> 9;
        int rem = o & 511;
        int h = rem >> 6;
        int e = rem & 63;
        float acc = sb[e];
#pragma unroll
        for (int c = 0; c < 32; c++) acc += sm[r][h * 32 + c] * sw[c * 64 + e];
        acc = fmaxf(acc, 0.0f);
        int row = r0 + r;
        int b = row >> 10, l = row & 1023;
        int bh = b * 8 + h;
        if (e < 32) q[((long)bh * LSEQ + l) * 32 + e] = acc;
        else        kt[((long)bh * 32 + (e - 32)) * LSEQ + l] = acc;
    }
}

// ======== shared phase-1 helper: scores + softmax into S (in smem) ==========
// A: workspace >= 8832 floats (Qs[32*16] at A, Kg[32][260] at A+512)
// S: [16][1028]
__device__ __forceinline__ void score_softmax_phase(
    const float* __restrict__ q, const float* __restrict__ kt,
    float* A, float* S, int bh, int r0, int t)
{
    float* Qs = A;
    float* Kg = A + 512;
    if (t < 128) {
        int r = t >> 3, k4 = (t & 7) * 4;
        float4 v = *(const float4*)(q + ((long)bh * LSEQ + r0 + r) * 32 + k4);
        Qs[(k4 + 0) * 16 + r] = v.x;
        Qs[(k4 + 1) * 16 + r] = v.y;
        Qs[(k4 + 2) * 16 + r] = v.z;
        Qs[(k4 + 3) * 16 + r] = v.w;
    }
    int tx = t & 63, ty = t >> 6;
    const float alpha = 1.0f / 32.0f;    // DIM^-0.5 / 2
    for (int g = 0; g < 4; g++) {
        __syncthreads();
        {
            int k = t >> 3;
            const float* src = kt + ((long)bh * 32 + k) * LSEQ + g * 256;
            float* dst = Kg + k * 260;
#pragma unroll
            for (int j = 0; j < 8; j++) {
                int c = ((t & 7) + 8 * j) * 4;
                *(float4*)(dst + c) = *(const float4*)(src + c);
            }
        }
        __syncthreads();
        float acc[4][4] = {};
#pragma unroll
        for (int k = 0; k < 32; k++) {
            float4 a = *(const float4*)&Qs[k * 16 + (ty << 2)];
            float4 b = *(const float4*)&Kg[k * 260 + (tx << 2)];
            acc[0][0] += a.x * b.x; acc[0][1] += a.x * b.y; acc[0][2] += a.x * b.z; acc[0][3] += a.x * b.w;
            acc[1][0] += a.y * b.x; acc[1][1] += a.y * b.y; acc[1][2] += a.y * b.z; acc[1][3] += a.y * b.w;
            acc[2][0] += a.z * b.x; acc[2][1] += a.z * b.y; acc[2][2] += a.z * b.z; acc[2][3] += a.z * b.w;
            acc[3][0] += a.w * b.x; acc[3][1] += a.w * b.y; acc[3][2] += a.w * b.z; acc[3][3] += a.w * b.w;
        }
#pragma unroll
        for (int i = 0; i < 4; i++) {
            float4 v;
            v.x = acc[i][0] * alpha; v.y = acc[i][1] * alpha;
            v.z = acc[i][2] * alpha; v.w = acc[i][3] * alpha;
            *(float4*)&S[((ty << 2) + i) * 1028 + g * 256 + (tx << 2)] = v;
        }
    }
    __syncthreads();
    // softmax: each warp 2 rows
    int warp = t >> 5, lane = t & 31;
    for (int rr = 0; rr < 2; rr++) {
        int row = warp * 2 + rr;
        float* sp = S + row * 1028;
        float v[32];
        float mx = -INFINITY;
#pragma unroll
        for (int j = 0; j < 32; j++) { v[j] = sp[lane + 32 * j]; mx = fmaxf(mx, v[j]); }
#pragma unroll
        for (int o = 16; o; o >>= 1) mx = fmaxf(mx, __shfl_xor_sync(0xffffffffu, mx, o));
        float s = 0.0f;
#pragma unroll
        for (int j = 0; j < 32; j++) { v[j] = expf(v[j] - mx); s += v[j]; }
#pragma unroll
        for (int o = 16; o; o >>= 1) s += __shfl_xor_sync(0xffffffffu, s, o);
        float inv = 1.0f / s;
#pragma unroll
        for (int j = 0; j < 32; j++) sp[lane + 32 * j] = v[j] * inv;
    }
    __syncthreads();
}

// ---------------- layer-3: attention probs written to out -------------------
__global__ __launch_bounds__(256, 2) void attn_kernel(
    const float* __restrict__ q, const float* __restrict__ kt,
    float* __restrict__ out)
{
    extern __shared__ float smem[];
    float* A = smem;
    float* S = smem + 9216;
    int t = threadIdx.x;
    int bh = blockIdx.y;
    int r0 = blockIdx.x * 16;
    score_softmax_phase(q, kt, A, S, bh, r0, t);
    float* op = out + ((long)bh * LSEQ + r0) * LSEQ;
#pragma unroll
    for (int j = 0; j < 16; j++) {
        int f = j * 256 + t;
        int row = f >> 8;
        int col = (f & 255) * 4;
        float4 v = *(const float4*)&S[row * 1028 + col];
        *(float4*)(op + (long)row * LSEQ + col) = v;
    }
}

// ---------------- layers 0-2: fused score+softmax+PV+residual ---------------
// mv[r0..r0+16, head h] = P @ xh + xh, written to mv_out (layout [b][l][256])
__global__ __launch_bounds__(256, 2) void attn_mv_kernel(
    const float* __restrict__ q, const float* __restrict__ kt,
    const float* __restrict__ xn, float* __restrict__ mv_out)
{
    extern __shared__ float smem[];
    float* A = smem;               // phase1: Qs+Kg (8832), phase2: X[256][36]=9216
    float* S = smem + 9216;        // [16][1028]
    int t = threadIdx.x;
    int bh = blockIdx.y;
    int r0 = blockIdx.x * 16;
    int b = bh >> 3, h = bh & 7;
    score_softmax_phase(q, kt, A, S, bh, r0, t);

    const float* xh = xn + (long)b * LSEQ * DIMC + h * 32;
    int g2 = t >> 6;               // 4 K-split groups of 64 threads
    int r2 = (t >> 3) & 7;         // 8 row-pairs -> rows 2r2, 2r2+1
    int c2 = t & 7;                // 8 col-quads -> cols 4c2..4c2+3
    float acc0[4] = {}, acc1[4] = {};
    for (int chunk = 0; chunk < 4; chunk++) {
        // load X[256][32] (stride 36) from xh rows chunk*256..+255
#pragma unroll
        for (int p = 0; p < 8; p++) {
            int row = (t >> 3) + 32 * p;
            int c4 = (t & 7) * 4;
            *(float4*)&A[row * 36 + c4] =
                *(const float4*)(xh + (long)(chunk * 256 + row) * DIMC + c4);
        }
        __syncthreads();
        const float* s0p = &S[(2 * r2) * 1028 + chunk * 256 + g2 * 64];
        const float* s1p = s0p + 1028;
#pragma unroll 8
        for (int tt = 0; tt < 64; tt++) {
            int tl = g2 * 64 + tt;
            float s0 = s0p[tt];
            float s1 = s1p[tt];
            float4 xv = *(const float4*)&A[tl * 36 + (c2 << 2)];
            acc0[0] += s0 * xv.x; acc0[1] += s0 * xv.y; acc0[2] += s0 * xv.z; acc0[3] += s0 * xv.w;
            acc1[0] += s1 * xv.x; acc1[1] += s1 * xv.y; acc1[2] += s1 * xv.z; acc1[3] += s1 * xv.w;
        }
        __syncthreads();
    }
    // write per-group partials into A[g2*512 + row*32 + col]
    *(float4*)&A[g2 * 512 + (2 * r2) * 32 + (c2 << 2)] =
        make_float4(acc0[0], acc0[1], acc0[2], acc0[3]);
    *(float4*)&A[g2 * 512 + (2 * r2 + 1) * 32 + (c2 << 2)] =
        make_float4(acc1[0], acc1[1], acc1[2], acc1[3]);
    __syncthreads();
#pragma unroll
    for (int rep = 0; rep < 2; rep++) {
        int o = t + 256 * rep;
        float val = A[o] + A[512 + o] + A[1024 + o] + A[1536 + o];
        int row = o >> 5, col = o & 31;
        long gi = ((long)(b * LSEQ + r0 + row)) * DIMC + h * 32 + col;
        mv_out[gi] = val + xn[gi];
    }
}

// ---------------- v = gelu(relu(mv_h @ vW(32x32) + vb)) ---------------------
__global__ __launch_bounds__(256) void v_kernel(
    const float* __restrict__ mv, const float* __restrict__ W,
    const float* __restrict__ bias, float* __restrict__ out)
{
    __shared__ float sm[16][DIMC];
    __shared__ float sw[32 * 32];
    __shared__ float sb[32];
    int t = threadIdx.x;
    int r0 = blockIdx.x * 16;
    for (int i = t; i < 16 * DIMC; i += 256)
        sm[i >> 8][i & 255] = mv[(long)(r0 + (i >> 8)) * DIMC + (i & 255)];
    for (int i = t; i < 1024; i += 256) sw[i] = W[i];
    if (t < 32) sb[t] = bias[t];
    __syncthreads();
    for (int o = t; o < 4096; o += 256) {
        int r = o >> 8, col = o & 255;
        int h = col >> 5, d = col & 31;
        float acc = sb[d];
#pragma unroll
        for (int c = 0; c < 32; c++) acc += sm[r][h * 32 + c] * sw[c * 32 + d];
        acc = fmaxf(acc, 0.0f);
        out[(long)(r0 + r) * DIMC + col] = gelu_f(acc);
    }
}

// ---------------- host orchestration ----------------------------------------
extern "C" void kernel_launch(void* const* d_in, const int* in_sizes, int n_in,
                              void* d_out, int out_size)
{
    (void)in_sizes; (void)n_in; (void)out_size;
    const float* img    = (const float*)d_in[0];
    const float* adj    = (const float*)d_in[1];
    const float* conv_w = (const float*)d_in[3];
    const float* conv_b = (const float*)d_in[4];
    const float* bn_g   = (const float*)d_in[5];
    const float* bn_b   = (const float*)d_in[6];
    const float* emb_w  = (const float*)d_in[7];
    const float* emb_b  = (const float*)d_in[8];
    const float* ln_g   = (const float*)d_in[9];
    const float* ln_b   = (const float*)d_in[10];
    const float* qk_w   = (const float*)d_in[11];
    const float* qk_b   = (const float*)d_in[12];
    const float* v_w    = (const float*)d_in[13];
    const float* v_b    = (const float*)d_in[14];
    const float* proj_w = (const float*)d_in[15];
    float* out = (float*)d_out;

    float *p_conv, *p_part, *p_stats, *p_embin, *p_x, *p_xn, *p_m, *p_q, *p_kt, *p_v;
    cudaGetSymbolAddress((void**)&p_conv,  g_conv);
    cudaGetSymbolAddress((void**)&p_part,  g_part);
    cudaGetSymbolAddress((void**)&p_stats, g_stats);
    cudaGetSymbolAddress((void**)&p_embin, g_embin);
    cudaGetSymbolAddress((void**)&p_x,     g_x);
    cudaGetSymbolAddress((void**)&p_xn,    g_xn);
    cudaGetSymbolAddress((void**)&p_m,     g_m);
    cudaGetSymbolAddress((void**)&p_q,     g_q);
    cudaGetSymbolAddress((void**)&p_kt,    g_kt);
    cudaGetSymbolAddress((void**)&p_v,     g_v);

    const int ATTN_SMEM = (9216 + 16448) * 4;   // 102656 B, both attn kernels
    static int smem_set = 0;
    if (!smem_set) {
        cudaFuncSetAttribute(attn_kernel,
                             cudaFuncAttributeMaxDynamicSharedMemorySize, ATTN_SMEM);
        cudaFuncSetAttribute(attn_mv_kernel,
                             cudaFuncAttributeMaxDynamicSharedMemorySize, ATTN_SMEM);
        smem_set = 1;
    }

    conv_kernel<<<NPATCH, 256>>>(img, conv_w, conv_b, p_conv, p_part);
    bn_stats_kernel<<<ECH, 256>>>(p_part, p_stats);
    bn_gelu_pool_kernel<<<NPATCH, 256>>>(p_conv, p_stats, bn_g, bn_b, p_embin);

    // embedding: (8192x1024) @ (1024x256) + bias
    sgemm_db<<<dim3(DIMC / 64, NPATCH / 128, 1), 256>>>(
        p_embin, emb_w, emb_b, nullptr, p_x, PDIM,
        0, 0, 0, 0, PDIM, DIMC, 0, DIMC);

    const long LD = (long)LSEQ * DIMC;
    for (int i = 0; i < 4; i++) {
        ln_kernel<<<NPATCH, 256>>>(p_x, ln_g + i * DIMC, ln_b + i * DIMC, p_xn);
        // m = A @ xn + xn  per batch: M=1024, N=256, K=1024
        sgemm_db<<<dim3(DIMC / 64, LSEQ / 128, BATCH), 256>>>(
            adj, p_xn, nullptr, p_xn, p_m, LSEQ,
            0, LD, LD, LD, LSEQ, DIMC, DIMC, DIMC);
        qk_kernel<<<NPATCH / 16, 256>>>(p_m, qk_w + i * DHEAD * 2 * DHEAD,
                                        qk_b + i * 2 * DHEAD, p_q, p_kt);
        if (i < 3) {
            // fused score+softmax+PV+residual -> m (overwrites m)
            attn_mv_kernel<<<dim3(LSEQ / 16, BHDIM), 256, ATTN_SMEM>>>(
                p_q, p_kt, p_xn, p_m);
            v_kernel<<<NPATCH / 16, 256>>>(p_m, v_w + i * DHEAD * DHEAD,
                                           v_b + i * DHEAD, p_v);
            // x = v @ proj_w + xn : M=8192, N=256, K=256
            sgemm_db<<<dim3(DIMC / 64, NPATCH / 128, 1), 256>>>(
                p_v, proj_w + i * DIMC * DIMC, nullptr, p_xn, p_x, DIMC,
                0, 0, 0, 0, DIMC, DIMC, DIMC, DIMC);
        } else {
            attn_kernel<<<dim3(LSEQ / 16, BHDIM), 256, ATTN_SMEM>>>(p_q, p_kt, out);
        }
    }
}